// round 4
// baseline (speedup 1.0000x reference)
#include <cuda_runtime.h>
#include <stdint.h>

typedef unsigned long long u64;

#define IN_CH     128
#define OC        64
#define MAX_NODES 100000
#define BM        128
#define KC        32
#define XS_STRIDE 132   // 128 rows + 4 pad floats; multiple of 4 -> 16B-aligned row starts

// Scratch (allocation-free): per-node "has incoming edge" mask + dtype flag.
__device__ unsigned int g_mask[MAX_NODES];
__device__ int          g_is64;

// ---------------------------------------------------------------------------
// Detect whether edge_index buffer is int64 or int32.
// int64 view: values in [0,100000) -> every odd 32-bit word (high word) is 0.
// Check 128 odd words; all zero => int64. One warp, negligible cost.
__global__ void k_detect(const unsigned int* __restrict__ ei32) {
    unsigned int w = 0;
    #pragma unroll
    for (int i = threadIdx.x; i < 128; i += 32) w |= ei32[2 * i + 1];
    unsigned int any = __ballot_sync(0xffffffffu, w != 0u);
    if (threadIdx.x == 0) g_is64 = (any == 0u) ? 1 : 0;
}

__global__ void k_zero_mask(int n) {
    int i = blockIdx.x * blockDim.x + threadIdx.x;
    if (i < n) g_mask[i] = 0u;
}

// Scatter with bounds clamp: no data value can ever produce a wild store.
__global__ void k_scatter_mask(const long long* __restrict__ col64,
                               const int* __restrict__ col32,
                               int ne, int n) {
    int i = blockIdx.x * blockDim.x + threadIdx.x;
    if (i >= ne) return;
    long long v = g_is64 ? col64[i] : (long long)col32[i];
    if (v >= 0 && v < (long long)n) g_mask[(int)v] = 1u;
}

// Packed dual fp32 FMA (sm_100+): d.lo = a.lo*b.lo + c.lo ; d.hi = a.hi*b.hi + c.hi
__device__ __forceinline__ u64 ffma2(u64 a, u64 b, u64 c) {
    u64 d;
    asm("fma.rn.f32x2 %0, %1, %2, %3;" : "=l"(d) : "l"(a), "l"(b), "l"(c));
    return d;
}

// out[r, :] = mask[r] ? x[r, :] @ W : 0
// 256 threads -> tile of BM=128 rows x 64 cols.
// Thread (ty = tid>>3 in 0..31, tx = tid&7): rows ty*4..ty*4+3, cols tx*8..tx*8+7.
// Accumulators: u64 acc[rowpair][col], (even row, odd row) packed per f32x2 word.
__global__ __launch_bounds__(256) void k_gemm_mask(
    const float* __restrict__ x,
    const float* __restrict__ W,
    float* __restrict__ out,
    int n)
{
    __shared__ __align__(16) float xs[KC * XS_STRIDE];  // transposed: xs[k][row]
    __shared__ __align__(16) u64   wsd[KC * OC];        // W duplicated: wsd[k][c] = (w,w)

    const int tid  = threadIdx.x;
    const int tx   = tid & 7;
    const int ty   = tid >> 3;
    const int row0 = blockIdx.x * BM;

    u64 acc[2][8];
    #pragma unroll
    for (int i = 0; i < 2; i++)
        #pragma unroll
        for (int j = 0; j < 8; j++)
            acc[i][j] = 0ull;   // == (0.0f, 0.0f)

    #pragma unroll 1
    for (int kc = 0; kc < IN_CH; kc += KC) {
        // ---- stage x tile (transposed). Warp reads 4 rows x 128B contiguous.
        #pragma unroll
        for (int s = 0; s < 4; s++) {
            int r    = ty + s * 32;          // local row 0..127
            int grow = row0 + r;
            float4 v = make_float4(0.f, 0.f, 0.f, 0.f);
            if (grow < n)
                v = *reinterpret_cast<const float4*>(x + (size_t)grow * IN_CH + kc + tx * 4);
            xs[(tx * 4 + 0) * XS_STRIDE + r] = v.x;
            xs[(tx * 4 + 1) * XS_STRIDE + r] = v.y;
            xs[(tx * 4 + 2) * XS_STRIDE + r] = v.z;
            xs[(tx * 4 + 3) * XS_STRIDE + r] = v.w;
        }
        // ---- stage W chunk, pre-duplicated for the FFMA2 b-operand.
        #pragma unroll
        for (int s = 0; s < 8; s++) {
            int idx = tid + s * 256;          // 0..2047
            int kk  = idx >> 6;
            int cc  = idx & 63;
            unsigned int wi = __float_as_uint(W[(kc + kk) * OC + cc]);
            wsd[idx] = ((u64)wi << 32) | (u64)wi;
        }
        __syncthreads();

        // ---- mainloop: per k, 1 LDS.128 (x rowpair) + 4 LDS.128 (dup W) + 16 FFMA2
        #pragma unroll
        for (int k = 0; k < KC; k++) {
            ulonglong2 xp = *reinterpret_cast<const ulonglong2*>(xs + k * XS_STRIDE + ty * 4);
            const ulonglong2* wp = reinterpret_cast<const ulonglong2*>(wsd + k * OC + tx * 8);
            ulonglong2 w0 = wp[0], w1 = wp[1], w2 = wp[2], w3 = wp[3];

            acc[0][0] = ffma2(xp.x, w0.x, acc[0][0]);
            acc[0][1] = ffma2(xp.x, w0.y, acc[0][1]);
            acc[0][2] = ffma2(xp.x, w1.x, acc[0][2]);
            acc[0][3] = ffma2(xp.x, w1.y, acc[0][3]);
            acc[0][4] = ffma2(xp.x, w2.x, acc[0][4]);
            acc[0][5] = ffma2(xp.x, w2.y, acc[0][5]);
            acc[0][6] = ffma2(xp.x, w3.x, acc[0][6]);
            acc[0][7] = ffma2(xp.x, w3.y, acc[0][7]);

            acc[1][0] = ffma2(xp.y, w0.x, acc[1][0]);
            acc[1][1] = ffma2(xp.y, w0.y, acc[1][1]);
            acc[1][2] = ffma2(xp.y, w1.x, acc[1][2]);
            acc[1][3] = ffma2(xp.y, w1.y, acc[1][3]);
            acc[1][4] = ffma2(xp.y, w2.x, acc[1][4]);
            acc[1][5] = ffma2(xp.y, w2.y, acc[1][5]);
            acc[1][6] = ffma2(xp.y, w3.x, acc[1][6]);
            acc[1][7] = ffma2(xp.y, w3.y, acc[1][7]);
        }
        __syncthreads();
    }

    // ---- epilogue: unpack rowpairs via register moves, apply mask, float4 stores.
    const int rbase = row0 + ty * 4;
    #pragma unroll
    for (int l = 0; l < 4; l++) {
        int r = rbase + l;
        if (r >= n) continue;
        float m  = g_mask[r] ? 1.0f : 0.0f;
        int  rp  = l >> 1;
        bool hi  = (l & 1) != 0;
        float o[8];
        #pragma unroll
        for (int j = 0; j < 8; j++) {
            u64 p = acc[rp][j];
            unsigned int bits = hi ? (unsigned int)(p >> 32) : (unsigned int)p;
            o[j] = __uint_as_float(bits) * m;
        }
        float4* po = reinterpret_cast<float4*>(out + (size_t)r * OC + tx * 8);
        po[0] = make_float4(o[0], o[1], o[2], o[3]);
        po[1] = make_float4(o[4], o[5], o[6], o[7]);
    }
}

extern "C" void kernel_launch(void* const* d_in, const int* in_sizes, int n_in,
                              void* d_out, int out_size)
{
    // metadata order: x, edge_index, edge_attr, W, W_edge, a
    const float* x   = (const float*)d_in[0];
    const void*  ei  = d_in[1];                 // int64 OR int32 [2, E] — detected on device
    const float* W   = (const float*)d_in[3];   // [128, 64] row-major
    float*       out = (float*)d_out;

    const int n  = in_sizes[0] / IN_CH;   // 100000
    const int ne = in_sizes[1] / 2;       // 1600000 (element count is dtype-independent)

    const long long* col64 = (const long long*)ei + ne;  // second half under int64 view
    const int*       col32 = (const int*)ei + ne;        // second half under int32 view

    k_detect      <<<1, 32>>>((const unsigned int*)ei);
    k_zero_mask   <<<(n  + 255) / 256, 256>>>(n);
    k_scatter_mask<<<(ne + 255) / 256, 256>>>(col64, col32, ne, n);
    k_gemm_mask   <<<(n + BM - 1) / BM, 256>>>(x, W, out, n);
}

// round 5
// speedup vs baseline: 3.3775x; 3.3775x over previous
#include <cuda_runtime.h>
#include <stdint.h>

typedef unsigned long long u64;

#define IN_CH     128
#define OC        64
#define MAX_NODES 100000
#define BM        128
#define KC        32
#define XSTR      130   // 128 rows + 2 pad; ≡2 mod 32 → 2-way STS, conflict-free float2 LDS

__device__ unsigned int g_mask[MAX_NODES];
__device__ int          g_is64;

// Detect int64 vs int32 edge_index: int64 view has all-zero high words (ids < 1e5).
__global__ void k_detect(const unsigned int* __restrict__ ei32) {
    unsigned int w = 0;
    #pragma unroll
    for (int i = threadIdx.x; i < 128; i += 32) w |= ei32[2 * i + 1];
    unsigned int any = __ballot_sync(0xffffffffu, w != 0u);
    if (threadIdx.x == 0) g_is64 = (any == 0u) ? 1 : 0;
}

__global__ void k_zero_mask(int n) {
    int i = blockIdx.x * blockDim.x + threadIdx.x;
    if (i < n) g_mask[i] = 0u;
}

__global__ void k_scatter_mask(const long long* __restrict__ col64,
                               const int* __restrict__ col32,
                               int ne, int n) {
    int i = blockIdx.x * blockDim.x + threadIdx.x;
    if (i >= ne) return;
    long long v = g_is64 ? col64[i] : (long long)col32[i];
    if (v >= 0 && v < (long long)n) g_mask[(int)v] = 1u;
}

__device__ __forceinline__ u64 ffma2(u64 a, u64 b, u64 c) {
    u64 d;
    asm("fma.rn.f32x2 %0, %1, %2, %3;" : "=l"(d) : "l"(a), "l"(b), "l"(c));
    return d;
}
__device__ __forceinline__ u64 dup2(float a) {
    u64 d;
    asm("mov.b64 %0, {%1, %1};" : "=l"(d) : "f"(a));
    return d;
}

// out[r,:] = mask[r] ? x[r,:] @ W : 0
// 128 threads; tile BM=128 rows x 64 cols. Thread (cg = tid>>6, t = tid&63):
// rows 2t, 2t+1; cols cg*32 .. cg*32+31.
// Accumulators packed by COLUMN pair: acc[row][i] = (out[.,c], out[.,c+1]),
// so the FFMA2 b-operand is W's natural layout -> smem W reads are pure
// single-address broadcasts (conflict-free), x dup'd once per k via mov.b64.
__global__ __launch_bounds__(128, 4) void k_gemm_mask(
    const float* __restrict__ x,
    const float* __restrict__ W,
    float* __restrict__ out,
    int n)
{
    __shared__ __align__(16) float xs[KC * XSTR];  // transposed x: xs[k][row]
    __shared__ __align__(16) u64   ws[KC * 32];    // W chunk verbatim: ws[k][c/2]

    const int tid  = threadIdx.x;
    const int cg   = tid >> 6;     // 0..1 -> column half
    const int t    = tid & 63;     // 0..63 -> row pair
    const int row0 = blockIdx.x * BM;

    u64 acc0[16], acc1[16];
    #pragma unroll
    for (int i = 0; i < 16; i++) { acc0[i] = 0ull; acc1[i] = 0ull; }

    #pragma unroll 1
    for (int kc = 0; kc < IN_CH; kc += KC) {
        // ---- stage x tile transposed (coalesced 128B global segments)
        #pragma unroll
        for (int j = 0; j < 8; j++) {
            int f    = tid + j * 128;   // float4 id, 0..1023
            int r    = f >> 3;          // local row 0..127
            int c4   = f & 7;           // float4 within row chunk
            int grow = row0 + r;
            float4 v = make_float4(0.f, 0.f, 0.f, 0.f);
            if (grow < n)
                v = *reinterpret_cast<const float4*>(x + (size_t)grow * IN_CH + kc + c4 * 4);
            xs[(c4 * 4 + 0) * XSTR + r] = v.x;
            xs[(c4 * 4 + 1) * XSTR + r] = v.y;
            xs[(c4 * 4 + 2) * XSTR + r] = v.z;
            xs[(c4 * 4 + 3) * XSTR + r] = v.w;
        }
        // ---- stage W chunk verbatim (contiguous 8KB copy)
        {
            const float4* src = reinterpret_cast<const float4*>(W + kc * OC);
            float4*       dst = reinterpret_cast<float4*>(ws);
            #pragma unroll
            for (int j = 0; j < 4; j++)
                dst[tid + j * 128] = src[tid + j * 128];
        }
        __syncthreads();

        // ---- mainloop: per k: 1 LDS.64 (x) + 8 LDS.128 (W broadcast) + 32 FFMA2
        #pragma unroll 4
        for (int k = 0; k < KC; k++) {
            float2 xv = *reinterpret_cast<const float2*>(xs + k * XSTR + 2 * t);
            u64 x0 = dup2(xv.x);
            u64 x1 = dup2(xv.y);
            const ulonglong2* wp = reinterpret_cast<const ulonglong2*>(ws + k * 32 + cg * 16);
            #pragma unroll
            for (int j = 0; j < 8; j++) {
                ulonglong2 w = wp[j];
                acc0[2*j]   = ffma2(x0, w.x, acc0[2*j]);
                acc0[2*j+1] = ffma2(x0, w.y, acc0[2*j+1]);
                acc1[2*j]   = ffma2(x1, w.x, acc1[2*j]);
                acc1[2*j+1] = ffma2(x1, w.y, acc1[2*j+1]);
            }
        }
        __syncthreads();
    }

    // ---- epilogue: mask + float4 stores (cols cg*32+4j .. +3 from acc pairs)
    const int r0 = row0 + 2 * t;
    const int r1 = r0 + 1;
    const float m0 = (r0 < n && g_mask[r0]) ? 1.0f : 0.0f;
    const float m1 = (r1 < n && g_mask[r1]) ? 1.0f : 0.0f;

    #pragma unroll
    for (int j = 0; j < 8; j++) {
        if (r0 < n) {
            float2 a = *reinterpret_cast<float2*>(&acc0[2*j]);
            float2 b = *reinterpret_cast<float2*>(&acc0[2*j+1]);
            *reinterpret_cast<float4*>(out + (size_t)r0 * OC + cg * 32 + 4 * j) =
                make_float4(a.x * m0, a.y * m0, b.x * m0, b.y * m0);
        }
        if (r1 < n) {
            float2 a = *reinterpret_cast<float2*>(&acc1[2*j]);
            float2 b = *reinterpret_cast<float2*>(&acc1[2*j+1]);
            *reinterpret_cast<float4*>(out + (size_t)r1 * OC + cg * 32 + 4 * j) =
                make_float4(a.x * m1, a.y * m1, b.x * m1, b.y * m1);
        }
    }
}

extern "C" void kernel_launch(void* const* d_in, const int* in_sizes, int n_in,
                              void* d_out, int out_size)
{
    // metadata order: x, edge_index, edge_attr, W, W_edge, a
    const float* x   = (const float*)d_in[0];
    const void*  ei  = d_in[1];                 // int64 or int32 [2, E], detected on device
    const float* W   = (const float*)d_in[3];   // [128, 64] row-major
    float*       out = (float*)d_out;

    const int n  = in_sizes[0] / IN_CH;   // 100000
    const int ne = in_sizes[1] / 2;       // 1600000

    const long long* col64 = (const long long*)ei + ne;
    const int*       col32 = (const int*)ei + ne;

    k_detect      <<<1, 32>>>((const unsigned int*)ei);
    k_zero_mask   <<<(n  + 255) / 256, 256>>>(n);
    k_scatter_mask<<<(ne + 255) / 256, 256>>>(col64, col32, ne, n);
    k_gemm_mask   <<<(n + BM - 1) / BM, 128>>>(x, W, out, n);
}